// round 1
// baseline (speedup 1.0000x reference)
#include <cuda_runtime.h>
#include <math.h>

// Problem constants
#define B_DIM 16
#define H_DIM 56
#define W_DIM 56
#define C_DIM 512
#define NHEAD 8
#define HD 64
#define WS 4
#define NWIN 3136      // 16 * 14 * 14
#define NTOK 50176     // NWIN * 16
#define SCALE 0.04419417382415922f   // 512^-0.5

// ---------------- scratch (static device globals; no allocation) -----------
__device__ float g_qkv[(size_t)NTOK * 1536];   // qkv of local branch
__device__ float g_xh[(size_t)NTOK * 512];     // local attention output
__device__ float g_xavg[NWIN * 512];           // pooled window tokens
__device__ float g_vl[NWIN * 512];             // v of global branch (== x_l)
__device__ float g_yl[NWIN * 512];             // x_l @ Wp2^T  (per-window add)
__device__ int   g_rowidx[NTOK];               // gt -> token row in x / out

// ---------------- index map: window-token order -> spatial row -------------
__global__ void k_rowidx(int* __restrict__ ridx) {
    int gt = blockIdx.x * 256 + threadIdx.x;
    if (gt >= NTOK) return;
    int widx = gt >> 4, t = gt & 15;
    int b = widx / 196;
    int rem = widx % 196;
    int wh = rem / 14, ww = rem % 14;
    int row = wh * WS + (t >> 2);
    int col = ww * WS + (t & 3);
    ridx[gt] = (b * H_DIM + row) * W_DIM + col;
}

// ---------------- per-window average pooling -------------------------------
__global__ void k_avg(const float* __restrict__ x, const int* __restrict__ ridx,
                      float* __restrict__ xavg) {
    int widx = blockIdx.x;
    int c = threadIdx.x * 4;              // 128 threads cover 512 channels
    float4 s = make_float4(0.f, 0.f, 0.f, 0.f);
    #pragma unroll
    for (int t = 0; t < 16; t++) {
        const float4 v = *(const float4*)(x + (long)ridx[widx * 16 + t] * C_DIM + c);
        s.x += v.x; s.y += v.y; s.z += v.z; s.w += v.w;
    }
    const float inv = 1.0f / 16.0f;
    s.x *= inv; s.y *= inv; s.z *= inv; s.w *= inv;
    *(float4*)(xavg + (long)widx * C_DIM + c) = s;
}

// ---------------- generic C = A * B^T SGEMM --------------------------------
// A: [M, K] rows contiguous (optionally gathered through amap)
// B: [N, K] rows with stride ldb (so this is an NT gemm)
// C: [M, N] rows with stride ldc (optionally scattered through cmap)
// optional epilogue: += addwin[m>>4][n] and += bias[n]
// Requirements used by all call sites: K % 16 == 0, N % 128 == 0.
#define BM 128
#define BN 128
#define BK 16
#define TM 8
#define TN 8

__global__ __launch_bounds__(256)
void sgemm_nt(const float* __restrict__ A, int lda, const int* __restrict__ amap,
              const float* __restrict__ B, int ldb,
              float* __restrict__ C, int ldc, const int* __restrict__ cmap,
              const float* __restrict__ addwin, const float* __restrict__ bias,
              int M, int N, int K) {
    __shared__ float As[BK][BM];
    __shared__ float Bs[BK][BN];

    const int tid = threadIdx.x;
    const int bm = blockIdx.y * BM;
    const int bn = blockIdx.x * BN;
    const int tx = tid & 15;       // 0..15 -> N direction
    const int ty = tid >> 4;       // 0..15 -> M direction

    const int lrow = tid >> 2;            // 0..63
    const int lcol = (tid & 3) * 4;       // 0,4,8,12

    float acc[TM][TN];
    #pragma unroll
    for (int i = 0; i < TM; i++)
        #pragma unroll
        for (int j = 0; j < TN; j++) acc[i][j] = 0.f;

    for (int k0 = 0; k0 < K; k0 += BK) {
        // --- load A tile (transposed into smem) ---
        #pragma unroll
        for (int h = 0; h < 2; h++) {
            const int r = lrow + h * 64;
            const int m = bm + r;
            float4 av = make_float4(0.f, 0.f, 0.f, 0.f);
            if (m < M) {
                const long src = amap ? (long)amap[m] : (long)m;
                av = *(const float4*)(A + src * lda + k0 + lcol);
            }
            As[lcol + 0][r] = av.x;
            As[lcol + 1][r] = av.y;
            As[lcol + 2][r] = av.z;
            As[lcol + 3][r] = av.w;
        }
        // --- load B tile ---  (N tiles are always full at our call sites)
        #pragma unroll
        for (int h = 0; h < 2; h++) {
            const int r = lrow + h * 64;
            const int n = bn + r;
            const float4 bv = *(const float4*)(B + (long)n * ldb + k0 + lcol);
            Bs[lcol + 0][r] = bv.x;
            Bs[lcol + 1][r] = bv.y;
            Bs[lcol + 2][r] = bv.z;
            Bs[lcol + 3][r] = bv.w;
        }
        __syncthreads();

        #pragma unroll
        for (int k = 0; k < BK; k++) {
            float af[TM], bf[TN];
            *(float4*)&af[0] = *(const float4*)&As[k][ty * TM];
            *(float4*)&af[4] = *(const float4*)&As[k][ty * TM + 4];
            *(float4*)&bf[0] = *(const float4*)&Bs[k][tx * TN];
            *(float4*)&bf[4] = *(const float4*)&Bs[k][tx * TN + 4];
            #pragma unroll
            for (int i = 0; i < TM; i++)
                #pragma unroll
                for (int j = 0; j < TN; j++)
                    acc[i][j] = fmaf(af[i], bf[j], acc[i][j]);
        }
        __syncthreads();
    }

    // --- epilogue / store ---
    #pragma unroll
    for (int i = 0; i < TM; i++) {
        const int m = bm + ty * TM + i;
        if (m >= M) continue;
        const long orow = cmap ? (long)cmap[m] : (long)m;
        float* cp = C + orow * ldc + bn + tx * TN;
        float o[TN];
        #pragma unroll
        for (int j = 0; j < TN; j++) o[j] = acc[i][j];
        if (addwin) {
            const float* ap = addwin + (long)(m >> 4) * 512 + bn + tx * TN;
            #pragma unroll
            for (int j = 0; j < TN; j++) o[j] += ap[j];
        }
        if (bias) {
            const float* bp = bias + bn + tx * TN;
            #pragma unroll
            for (int j = 0; j < TN; j++) o[j] += bp[j];
        }
        *(float4*)(cp)     = make_float4(o[0], o[1], o[2], o[3]);
        *(float4*)(cp + 4) = make_float4(o[4], o[5], o[6], o[7]);
    }
}

// ---------------- 16x16 local window attention (per window, per head) ------
#define QK_PAD 68   // padded row stride for q/k/v smem tiles

__global__ __launch_bounds__(256)
void k_attn(const float* __restrict__ qkv, float* __restrict__ xh) {
    const int widx = blockIdx.x;
    const int h = blockIdx.y;

    __shared__ float q[16][QK_PAD];
    __shared__ float k[16][QK_PAD];
    __shared__ float v[16][QK_PAD];
    __shared__ float S[16][17];
    __shared__ float rmax[16], rsum[16];

    const int tid = threadIdx.x;
    const int t = tid >> 4;
    const int c4 = (tid & 15) * 4;

    const float* base = qkv + ((long)(widx * 16 + t)) * 1536 + h * HD + c4;
    *(float4*)&q[t][c4] = *(const float4*)(base);
    *(float4*)&k[t][c4] = *(const float4*)(base + 512);
    *(float4*)&v[t][c4] = *(const float4*)(base + 1024);
    __syncthreads();

    const int i = tid >> 4;
    const int j = tid & 15;
    float s = 0.f;
    #pragma unroll
    for (int d = 0; d < HD; d++) s = fmaf(q[i][d], k[j][d], s);
    S[i][j] = s * SCALE;
    __syncthreads();

    if (j == 0) {
        float m = S[i][0];
        #pragma unroll
        for (int jj = 1; jj < 16; jj++) m = fmaxf(m, S[i][jj]);
        rmax[i] = m;
    }
    __syncthreads();
    S[i][j] = expf(S[i][j] - rmax[i]);
    __syncthreads();
    if (j == 0) {
        float su = 0.f;
        #pragma unroll
        for (int jj = 0; jj < 16; jj++) su += S[i][jj];
        rsum[i] = 1.0f / su;
    }
    __syncthreads();

    // out[i][d] = sum_j P[i][j] * v[j][d];  1024 outputs over 256 threads
    #pragma unroll
    for (int it = 0; it < 4; it++) {
        const int idx = tid + it * 256;
        const int oi = idx >> 6;
        const int d = idx & 63;
        const float rs = rsum[oi];
        float acc = 0.f;
        #pragma unroll
        for (int jj = 0; jj < 16; jj++) acc = fmaf(S[oi][jj] * rs, v[jj][d], acc);
        xh[((long)(widx * 16 + oi)) * 512 + h * HD + d] = acc;
    }
}

// ---------------- launch ---------------------------------------------------
extern "C" void kernel_launch(void* const* d_in, const int* in_sizes, int n_in,
                              void* d_out, int out_size) {
    const float* x        = (const float*)d_in[0];
    const float* w_qkv_h  = (const float*)d_in[1];
    const float* w_qkv_l  = (const float*)d_in[2];
    const float* w_proj   = (const float*)d_in[3];
    const float* b_proj   = (const float*)d_in[4];
    float* out = (float*)d_out;

    float *qkv, *xh, *xavg, *vl, *yl;
    int* ridx;
    cudaGetSymbolAddress((void**)&qkv,  g_qkv);
    cudaGetSymbolAddress((void**)&xh,   g_xh);
    cudaGetSymbolAddress((void**)&xavg, g_xavg);
    cudaGetSymbolAddress((void**)&vl,   g_vl);
    cudaGetSymbolAddress((void**)&yl,   g_yl);
    cudaGetSymbolAddress((void**)&ridx, g_rowidx);

    // 1. token index map
    k_rowidx<<<(NTOK + 255) / 256, 256>>>(ridx);

    // 2. window average pooling
    k_avg<<<NWIN, 128>>>(x, ridx, xavg);

    // 3. global branch: softmax over 1 token == identity, so x_l = v_l.
    //    vl = xavg @ Wv_l^T    (Wv_l = rows [1024:1536) of w_qkv_l)
    sgemm_nt<<<dim3(512 / BN, (NWIN + BM - 1) / BM), 256>>>(
        xavg, 512, nullptr,
        w_qkv_l + (long)1024 * 512, 512,
        vl, 512, nullptr, nullptr, nullptr,
        NWIN, 512, 512);

    // 4. yl = vl @ Wp2^T       (Wp2 = w_proj[:, 512:1024], row stride 1024)
    sgemm_nt<<<dim3(512 / BN, (NWIN + BM - 1) / BM), 256>>>(
        vl, 512, nullptr,
        w_proj + 512, 1024,
        yl, 512, nullptr, nullptr, nullptr,
        NWIN, 512, 512);

    // 5. local branch qkv = gather(x) @ w_qkv_h^T  -> [NTOK, 1536]
    sgemm_nt<<<dim3(1536 / BN, NTOK / BM), 256>>>(
        x, 512, ridx,
        w_qkv_h, 512,
        qkv, 1536, nullptr, nullptr, nullptr,
        NTOK, 1536, 512);

    // 6. 16x16 window attention per (window, head)
    k_attn<<<dim3(NWIN, NHEAD), 256>>>(qkv, xh);

    // 7. out = scatter( xh @ Wp1^T + yl[window] + bias )
    sgemm_nt<<<dim3(512 / BN, NTOK / BM), 256>>>(
        xh, 512, nullptr,
        w_proj, 1024,
        out, 512, ridx, yl, b_proj,
        NTOK, 512, 512);
}

// round 2
// speedup vs baseline: 2.1070x; 2.1070x over previous
#include <cuda_runtime.h>
#include <math.h>
#include <stdint.h>

// Problem constants
#define B_DIM 16
#define H_DIM 56
#define W_DIM 56
#define C_DIM 512
#define NHEAD 8
#define HD 64
#define WS 4
#define NWIN 3136      // 16 * 14 * 14
#define NTOK 50176     // NWIN * 16
#define SCALE 0.04419417382415922f   // 512^-0.5

// ---------------- scratch (static device globals; no allocation) -----------
__device__ float g_qkv[(size_t)NTOK * 1536];   // qkv of local branch
__device__ float g_xh[(size_t)NTOK * 512];     // local attention output
__device__ float g_xavg[NWIN * 512];           // pooled window tokens
__device__ float g_vl[NWIN * 512];             // v of global branch (== x_l)
__device__ float g_yl[NWIN * 512];             // x_l @ Wp2^T  (per-window add)
__device__ int   g_rowidx[NTOK];               // gt -> token row in x / out

// ---------------- index map: window-token order -> spatial row -------------
__global__ void k_rowidx(int* __restrict__ ridx) {
    int gt = blockIdx.x * 256 + threadIdx.x;
    if (gt >= NTOK) return;
    int widx = gt >> 4, t = gt & 15;
    int b = widx / 196;
    int rem = widx % 196;
    int wh = rem / 14, ww = rem % 14;
    int row = wh * WS + (t >> 2);
    int col = ww * WS + (t & 3);
    ridx[gt] = (b * H_DIM + row) * W_DIM + col;
}

// ---------------- per-window average pooling -------------------------------
__global__ void k_avg(const float* __restrict__ x, const int* __restrict__ ridx,
                      float* __restrict__ xavg) {
    int widx = blockIdx.x;
    int c = threadIdx.x * 4;              // 128 threads cover 512 channels
    float4 s = make_float4(0.f, 0.f, 0.f, 0.f);
    #pragma unroll
    for (int t = 0; t < 16; t++) {
        const float4 v = *(const float4*)(x + (long)ridx[widx * 16 + t] * C_DIM + c);
        s.x += v.x; s.y += v.y; s.z += v.z; s.w += v.w;
    }
    const float inv = 1.0f / 16.0f;
    s.x *= inv; s.y *= inv; s.z *= inv; s.w *= inv;
    *(float4*)(xavg + (long)widx * C_DIM + c) = s;
}

// ---------------- tf32 tensor-core C = A * B^T GEMM ------------------------
// A: [M, K] fp32 rows (optionally gathered via amap)
// B: [N, K] fp32 rows with stride ldb  (NT gemm)
// C: [M, N] fp32 rows with stride ldc (optionally scattered via cmap)
// optional epilogue: += addwin[m>>4][n], += bias[n]
// Call-site invariants: K % 16 == 0, N % 128 == 0.
#define BM 128
#define BN 128
#define BK 16

__device__ __forceinline__ uint32_t f2tf32(float f) {
    uint32_t r;
    asm("cvt.rna.tf32.f32 %0, %1;" : "=r"(r) : "f"(f));
    return r;
}

__device__ __forceinline__ void mma_tf32(float c[4], const uint32_t a[4], const uint32_t b[2]) {
    asm volatile(
        "mma.sync.aligned.m16n8k8.row.col.f32.tf32.tf32.f32 "
        "{%0,%1,%2,%3}, {%4,%5,%6,%7}, {%8,%9}, {%0,%1,%2,%3};"
        : "+f"(c[0]), "+f"(c[1]), "+f"(c[2]), "+f"(c[3])
        : "r"(a[0]), "r"(a[1]), "r"(a[2]), "r"(a[3]), "r"(b[0]), "r"(b[1]));
}

__global__ __launch_bounds__(256, 2)
void tgemm_nt(const float* __restrict__ A, int lda, const int* __restrict__ amap,
              const float* __restrict__ B, int ldb,
              float* __restrict__ C, int ldc, const int* __restrict__ cmap,
              const float* __restrict__ addwin, const float* __restrict__ bias,
              int M, int N, int K) {
    __shared__ uint32_t As[BK][BM + 4];   // [k][m]  (A transposed)
    __shared__ uint32_t Bs[BK][BN + 4];   // [k][n]

    const int tid  = threadIdx.x;
    const int warp = tid >> 5;
    const int lane = tid & 31;
    const int g = lane >> 2;          // group id 0..7
    const int q = lane & 3;           // thread in group 0..3
    const int wm = (warp >> 2) * 64;  // warp tile origin (2 warps in M)
    const int wn = (warp & 3) * 32;   // 4 warps in N

    const int bm = blockIdx.y * BM;
    const int bn = blockIdx.x * BN;

    // loader mapping: 256 threads, each loads 2 float4 for A and 2 for B
    const int lr = tid >> 2;            // 0..63
    const int lc = (tid & 3) * 4;       // 0,4,8,12

    float acc[4][4][4];                 // [mtile][ntile][reg]
    #pragma unroll
    for (int t = 0; t < 4; t++)
        #pragma unroll
        for (int u = 0; u < 4; u++)
            #pragma unroll
            for (int r = 0; r < 4; r++) acc[t][u][r] = 0.f;

    float4 pa[2], pb[2];

    // prefetch first tile
    #pragma unroll
    for (int h = 0; h < 2; h++) {
        const int m = bm + lr + h * 64;
        if (m < M) {
            const long src = amap ? (long)amap[m] : (long)m;
            pa[h] = *(const float4*)(A + src * lda + lc);
        } else pa[h] = make_float4(0.f, 0.f, 0.f, 0.f);
        const int n = bn + lr + h * 64;
        pb[h] = *(const float4*)(B + (long)n * ldb + lc);
    }

    for (int k0 = 0; k0 < K; k0 += BK) {
        // store prefetched tile to smem (with tf32 rounding)
        #pragma unroll
        for (int h = 0; h < 2; h++) {
            const int r = lr + h * 64;
            As[lc + 0][r] = f2tf32(pa[h].x);
            As[lc + 1][r] = f2tf32(pa[h].y);
            As[lc + 2][r] = f2tf32(pa[h].z);
            As[lc + 3][r] = f2tf32(pa[h].w);
            Bs[lc + 0][r] = f2tf32(pb[h].x);
            Bs[lc + 1][r] = f2tf32(pb[h].y);
            Bs[lc + 2][r] = f2tf32(pb[h].z);
            Bs[lc + 3][r] = f2tf32(pb[h].w);
        }
        __syncthreads();

        // prefetch next tile
        if (k0 + BK < K) {
            const int kn = k0 + BK;
            #pragma unroll
            for (int h = 0; h < 2; h++) {
                const int m = bm + lr + h * 64;
                if (m < M) {
                    const long src = amap ? (long)amap[m] : (long)m;
                    pa[h] = *(const float4*)(A + src * lda + kn + lc);
                } else pa[h] = make_float4(0.f, 0.f, 0.f, 0.f);
                const int n = bn + lr + h * 64;
                pb[h] = *(const float4*)(B + (long)n * ldb + kn + lc);
            }
        }

        // compute: two k8 steps
        #pragma unroll
        for (int kk = 0; kk < 2; kk++) {
            const int kb = kk * 8;
            uint32_t af[4][4];
            #pragma unroll
            for (int t = 0; t < 4; t++) {
                const int m = wm + t * 16 + g;
                af[t][0] = As[kb + q][m];
                af[t][1] = As[kb + q][m + 8];
                af[t][2] = As[kb + q + 4][m];
                af[t][3] = As[kb + q + 4][m + 8];
            }
            uint32_t bf[4][2];
            #pragma unroll
            for (int u = 0; u < 4; u++) {
                const int n = wn + u * 8 + g;
                bf[u][0] = Bs[kb + q][n];
                bf[u][1] = Bs[kb + q + 4][n];
            }
            #pragma unroll
            for (int t = 0; t < 4; t++)
                #pragma unroll
                for (int u = 0; u < 4; u++)
                    mma_tf32(acc[t][u], af[t], bf[u]);
        }
        __syncthreads();
    }

    // --- epilogue / store ---
    #pragma unroll
    for (int t = 0; t < 4; t++) {
        #pragma unroll
        for (int half = 0; half < 2; half++) {
            const int m = bm + wm + t * 16 + g + half * 8;
            if (m >= M) continue;
            const long orow = cmap ? (long)cmap[m] : (long)m;
            const int colb = bn + wn + 2 * q;
            const float* ap = addwin ? addwin + (long)(m >> 4) * 512 : nullptr;
            #pragma unroll
            for (int u = 0; u < 4; u++) {
                const int col = colb + u * 8;
                float o0 = acc[t][u][half * 2 + 0];
                float o1 = acc[t][u][half * 2 + 1];
                if (ap)   { o0 += ap[col];   o1 += ap[col + 1]; }
                if (bias) { o0 += bias[col]; o1 += bias[col + 1]; }
                *(float2*)(C + orow * ldc + col) = make_float2(o0, o1);
            }
        }
    }
}

// ---------------- 16x16 local window attention (per window, per head) ------
#define QK_PAD 68   // padded row stride for q/k/v smem tiles

__global__ __launch_bounds__(256)
void k_attn(const float* __restrict__ qkv, float* __restrict__ xh) {
    const int widx = blockIdx.x;
    const int h = blockIdx.y;

    __shared__ float q[16][QK_PAD];
    __shared__ float k[16][QK_PAD];
    __shared__ float v[16][QK_PAD];
    __shared__ float S[16][17];
    __shared__ float rmax[16], rsum[16];

    const int tid = threadIdx.x;
    const int t = tid >> 4;
    const int c4 = (tid & 15) * 4;

    const float* base = qkv + ((long)(widx * 16 + t)) * 1536 + h * HD + c4;
    *(float4*)&q[t][c4] = *(const float4*)(base);
    *(float4*)&k[t][c4] = *(const float4*)(base + 512);
    *(float4*)&v[t][c4] = *(const float4*)(base + 1024);
    __syncthreads();

    const int i = tid >> 4;
    const int j = tid & 15;
    float s = 0.f;
    #pragma unroll
    for (int d = 0; d < HD; d++) s = fmaf(q[i][d], k[j][d], s);
    S[i][j] = s * SCALE;
    __syncthreads();

    if (j == 0) {
        float m = S[i][0];
        #pragma unroll
        for (int jj = 1; jj < 16; jj++) m = fmaxf(m, S[i][jj]);
        rmax[i] = m;
    }
    __syncthreads();
    S[i][j] = expf(S[i][j] - rmax[i]);
    __syncthreads();
    if (j == 0) {
        float su = 0.f;
        #pragma unroll
        for (int jj = 0; jj < 16; jj++) su += S[i][jj];
        rsum[i] = 1.0f / su;
    }
    __syncthreads();

    #pragma unroll
    for (int it = 0; it < 4; it++) {
        const int idx = tid + it * 256;
        const int oi = idx >> 6;
        const int d = idx & 63;
        const float rs = rsum[oi];
        float acc = 0.f;
        #pragma unroll
        for (int jj = 0; jj < 16; jj++) acc = fmaf(S[oi][jj] * rs, v[jj][d], acc);
        xh[((long)(widx * 16 + oi)) * 512 + h * HD + d] = acc;
    }
}

// ---------------- launch ---------------------------------------------------
extern "C" void kernel_launch(void* const* d_in, const int* in_sizes, int n_in,
                              void* d_out, int out_size) {
    const float* x        = (const float*)d_in[0];
    const float* w_qkv_h  = (const float*)d_in[1];
    const float* w_qkv_l  = (const float*)d_in[2];
    const float* w_proj   = (const float*)d_in[3];
    const float* b_proj   = (const float*)d_in[4];
    float* out = (float*)d_out;

    float *qkv, *xh, *xavg, *vl, *yl;
    int* ridx;
    cudaGetSymbolAddress((void**)&qkv,  g_qkv);
    cudaGetSymbolAddress((void**)&xh,   g_xh);
    cudaGetSymbolAddress((void**)&xavg, g_xavg);
    cudaGetSymbolAddress((void**)&vl,   g_vl);
    cudaGetSymbolAddress((void**)&yl,   g_yl);
    cudaGetSymbolAddress((void**)&ridx, g_rowidx);

    // 1. token index map
    k_rowidx<<<(NTOK + 255) / 256, 256>>>(ridx);

    // 2. window average pooling
    k_avg<<<NWIN, 128>>>(x, ridx, xavg);

    // 3. global branch: softmax over 1 token == identity, so x_l = v_l.
    //    vl = xavg @ Wv_l^T    (Wv_l = rows [1024:1536) of w_qkv_l)
    tgemm_nt<<<dim3(512 / BN, (NWIN + BM - 1) / BM), 256>>>(
        xavg, 512, nullptr,
        w_qkv_l + (long)1024 * 512, 512,
        vl, 512, nullptr, nullptr, nullptr,
        NWIN, 512, 512);

    // 4. yl = vl @ Wp2^T       (Wp2 = w_proj[:, 512:1024], row stride 1024)
    tgemm_nt<<<dim3(512 / BN, (NWIN + BM - 1) / BM), 256>>>(
        vl, 512, nullptr,
        w_proj + 512, 1024,
        yl, 512, nullptr, nullptr, nullptr,
        NWIN, 512, 512);

    // 5. local branch qkv = gather(x) @ w_qkv_h^T  -> [NTOK, 1536]
    tgemm_nt<<<dim3(1536 / BN, NTOK / BM), 256>>>(
        x, 512, ridx,
        w_qkv_h, 512,
        qkv, 1536, nullptr, nullptr, nullptr,
        NTOK, 1536, 512);

    // 6. 16x16 window attention per (window, head)
    k_attn<<<dim3(NWIN, NHEAD), 256>>>(qkv, xh);

    // 7. out = scatter( xh @ Wp1^T + yl[window] + bias )
    tgemm_nt<<<dim3(512 / BN, NTOK / BM), 256>>>(
        xh, 512, nullptr,
        w_proj, 1024,
        out, 512, ridx, yl, b_proj,
        NTOK, 512, 512);
}

// round 4
// speedup vs baseline: 3.7298x; 1.7701x over previous
#include <cuda_runtime.h>
#include <math.h>
#include <stdint.h>

// Problem constants
#define B_DIM 16
#define H_DIM 56
#define W_DIM 56
#define C_DIM 512
#define NHEAD 8
#define HD 64
#define WS 4
#define NWIN 3136      // 16 * 14 * 14
#define NTOK 50176     // NWIN * 16
#define SCALE 0.04419417382415922f   // 512^-0.5

// ---------------- scratch (static device globals; no allocation) -----------
__device__ float g_qkv[(size_t)NTOK * 1536];   // qkv of local branch
__device__ float g_xg[(size_t)NTOK * 512];     // gathered + tf32-rounded x
__device__ float g_xh[(size_t)NTOK * 512];     // local attention out (rounded)
__device__ float g_xavg[NWIN * 512];           // pooled window tokens (rounded)
__device__ float g_vl[NWIN * 512];             // v of global branch (rounded)
__device__ float g_yl[NWIN * 512];             // vl @ Wp2^T (per-window add)
__device__ float g_wqkv[1536 * 512];           // rounded w_qkv_h
__device__ float g_wvl[512 * 512];             // rounded w_qkv_l v-part
__device__ float g_wp1[512 * 512];             // rounded w_proj[:, :512]
__device__ float g_wp2[512 * 512];             // rounded w_proj[:, 512:]
__device__ int   g_rowidx[NTOK];               // gt -> token row in x / out

// ---------------- small helpers --------------------------------------------
__device__ __forceinline__ float tf32r(float f) {
    uint32_t r;
    asm("cvt.rna.tf32.f32 %0, %1;" : "=r"(r) : "f"(f));
    return __uint_as_float(r);
}

__device__ __forceinline__ uint32_t smem_u32(const void* p) {
    uint32_t a;
    asm("{ .reg .u64 t; cvta.to.shared.u64 t, %1; cvt.u32.u64 %0, t; }" : "=r"(a) : "l"(p));
    return a;
}

__device__ __forceinline__ void cpasync16(uint32_t dst, const void* src) {
    asm volatile("cp.async.cg.shared.global [%0], [%1], 16;" :: "r"(dst), "l"(src) : "memory");
}

__device__ __forceinline__ void ldsm_x4(uint32_t r[4], uint32_t addr) {
    asm volatile("ldmatrix.sync.aligned.m8n8.x4.shared.b16 {%0,%1,%2,%3}, [%4];"
                 : "=r"(r[0]), "=r"(r[1]), "=r"(r[2]), "=r"(r[3]) : "r"(addr));
}

__device__ __forceinline__ void mma_tf32(float c[4], const uint32_t a[4], const uint32_t b[2]) {
    asm volatile(
        "mma.sync.aligned.m16n8k8.row.col.f32.tf32.tf32.f32 "
        "{%0,%1,%2,%3}, {%4,%5,%6,%7}, {%8,%9}, {%0,%1,%2,%3};"
        : "+f"(c[0]), "+f"(c[1]), "+f"(c[2]), "+f"(c[3])
        : "r"(a[0]), "r"(a[1]), "r"(a[2]), "r"(a[3]), "r"(b[0]), "r"(b[1]));
}

// ---------------- index map: window-token order -> spatial row -------------
__global__ void k_rowidx(int* __restrict__ ridx) {
    int gt = blockIdx.x * 256 + threadIdx.x;
    if (gt >= NTOK) return;
    int widx = gt >> 4, t = gt & 15;
    int b = widx / 196;
    int rem = widx % 196;
    int wh = rem / 14, ww = rem % 14;
    int row = wh * WS + (t >> 2);
    int col = ww * WS + (t & 3);
    ridx[gt] = (b * H_DIM + row) * W_DIM + col;
}

// ---------------- gather x into window order + tf32 round ------------------
__global__ void k_gather(const float* __restrict__ x, const int* __restrict__ ridx,
                         float* __restrict__ xg) {
    int gt = blockIdx.x * 2 + (threadIdx.x >> 7);
    int c = (threadIdx.x & 127) * 4;
    const float4 v = *(const float4*)(x + (size_t)ridx[gt] * C_DIM + c);
    float4 o = make_float4(tf32r(v.x), tf32r(v.y), tf32r(v.z), tf32r(v.w));
    *(float4*)(xg + (size_t)gt * C_DIM + c) = o;
}

// ---------------- per-window average pooling (rounded output) --------------
__global__ void k_avg(const float* __restrict__ x, const int* __restrict__ ridx,
                      float* __restrict__ xavg) {
    int widx = blockIdx.x;
    int c = threadIdx.x * 4;
    float4 s = make_float4(0.f, 0.f, 0.f, 0.f);
    #pragma unroll
    for (int t = 0; t < 16; t++) {
        const float4 v = *(const float4*)(x + (size_t)ridx[widx * 16 + t] * C_DIM + c);
        s.x += v.x; s.y += v.y; s.z += v.z; s.w += v.w;
    }
    const float inv = 1.0f / 16.0f;
    float4 o = make_float4(tf32r(s.x * inv), tf32r(s.y * inv),
                           tf32r(s.z * inv), tf32r(s.w * inv));
    *(float4*)(xavg + (size_t)widx * C_DIM + c) = o;
}

// ---------------- weight rounding / packing --------------------------------
__global__ void k_roundcopy(const float* __restrict__ src, float* __restrict__ dst, int n4) {
    int i = blockIdx.x * 256 + threadIdx.x;
    if (i >= n4) return;
    float4 v = *(const float4*)(src + (size_t)i * 4);
    *(float4*)(dst + (size_t)i * 4) =
        make_float4(tf32r(v.x), tf32r(v.y), tf32r(v.z), tf32r(v.w));
}

__global__ void k_packproj(const float* __restrict__ wproj,
                           float* __restrict__ wp1, float* __restrict__ wp2) {
    int i = blockIdx.x * 256 + threadIdx.x;   // 512*128 float4s
    if (i >= 512 * 128) return;
    int n = i >> 7, k4 = (i & 127) * 4;
    float4 a = *(const float4*)(wproj + (size_t)n * 1024 + k4);
    float4 b = *(const float4*)(wproj + (size_t)n * 1024 + 512 + k4);
    *(float4*)(wp1 + (size_t)n * 512 + k4) =
        make_float4(tf32r(a.x), tf32r(a.y), tf32r(a.z), tf32r(a.w));
    *(float4*)(wp2 + (size_t)n * 512 + k4) =
        make_float4(tf32r(b.x), tf32r(b.y), tf32r(b.z), tf32r(b.w));
}

// ---------------- tf32 tensor GEMM: C = A * B^T ----------------------------
// A: [M, 512] tf32-rounded fp32 (rows clamped at M edge)
// B: [N, 512] tf32-rounded fp32, N multiple of 128
// C: [M, ldc] optional row scatter (cmap), += addwin[m>>4][col], += bias[col],
//    optional tf32 rounding of the output.
// BM=BN=128, BK=32, double-buffered cp.async, ldmatrix fragment loads.
// Warp tile 64x32: warps 2(M) x 4(N); per warp 4x4 m16n8 tiles.
#define GBM 128
#define GBN 128
#define GBK 32
#define GK  512
#define NSTG (GK / GBK)        // 16 k-slabs
#define STG_BYTES 32768        // (128 A rows + 128 B rows) * 128 B

__global__ __launch_bounds__(256, 2)
void tc_gemm(const float* __restrict__ A, const float* __restrict__ B,
             float* __restrict__ C, int ldc,
             const int* __restrict__ cmap, const float* __restrict__ addwin,
             const float* __restrict__ bias, int M, int roundOut) {
    extern __shared__ char smem[];
    const uint32_t sbase = smem_u32(smem);

    const int tid  = threadIdx.x;
    const int warp = tid >> 5;
    const int lane = tid & 31;
    const int g = lane >> 2;
    const int q = lane & 3;
    const int wm = (warp >> 2) * 64;
    const int wn = (warp & 3) * 32;
    const int bm = blockIdx.y * GBM;
    const int bn = blockIdx.x * GBN;

    // ldmatrix address components (swizzle: off ^= (row&7)<<4 on the column)
    const int mid = lane >> 3;          // matrix id 0..3
    const int r7  = lane & 7;
    // A: matrices (rows g / g+8) x (cols q / q+4)
    const int aRow0 = wm + (mid & 1) * 8 + r7;       // + t*16
    const int aHalf = (mid >> 1) * 16;               // byte col half
    // B: matrices (n-rows u / u+8) x (cols q / q+4)
    const int bRow0 = wn + (mid >> 1) * 8 + r7;      // + upair*16
    const int bHalf = (mid & 1) * 16;

    float acc[4][4][4];
    #pragma unroll
    for (int t = 0; t < 4; t++)
        #pragma unroll
        for (int u = 0; u < 4; u++)
            #pragma unroll
            for (int r = 0; r < 4; r++) acc[t][u][r] = 0.f;

    // stage loader: 4 A-chunks + 4 B-chunks of 16B per thread
    auto load_stage = [&](int s, int buf) {
        const int k0 = s * GBK;
        const uint32_t so = sbase + buf * STG_BYTES;
        #pragma unroll
        for (int i = 0; i < 4; i++) {
            int idx = tid + i * 256;          // 0..1023
            int r = idx >> 3, hc = idx & 7;
            int grow = bm + r; if (grow >= M) grow = M - 1;
            uint32_t off = (uint32_t)(r * 128 + hc * 16);
            cpasync16(so + (off ^ ((off >> 3) & 0x70)),
                      A + (size_t)grow * GK + k0 + hc * 4);
        }
        #pragma unroll
        for (int i = 0; i < 4; i++) {
            int idx = tid + i * 256;
            int r = idx >> 3, hc = idx & 7;
            uint32_t off = (uint32_t)(r * 128 + hc * 16);
            cpasync16(so + 16384 + (off ^ ((off >> 3) & 0x70)),
                      B + (size_t)(bn + r) * GK + k0 + hc * 4);
        }
        asm volatile("cp.async.commit_group;" ::: "memory");
    };

    load_stage(0, 0);
    load_stage(1, 1);

    for (int s = 0; s < NSTG; s++) {
        const int buf = s & 1;
        if (s < NSTG - 1) asm volatile("cp.async.wait_group 1;" ::: "memory");
        else              asm volatile("cp.async.wait_group 0;" ::: "memory");
        __syncthreads();

        const uint32_t sA = sbase + buf * STG_BYTES;
        const uint32_t sB = sA + 16384;

        #pragma unroll
        for (int kk = 0; kk < 4; kk++) {
            const uint32_t acol = (uint32_t)(kk * 32 + aHalf);
            const uint32_t bcol = (uint32_t)(kk * 32 + bHalf);
            uint32_t af[4][4];
            #pragma unroll
            for (int t = 0; t < 4; t++) {
                const uint32_t row = (uint32_t)(aRow0 + t * 16);
                ldsm_x4(af[t], sA + (row << 7) + (((row & 7) << 4) ^ acol));
            }
            uint32_t bf[4][2];
            #pragma unroll
            for (int up = 0; up < 2; up++) {
                uint32_t r4[4];
                const uint32_t row = (uint32_t)(bRow0 + up * 16);
                ldsm_x4(r4, sB + (row << 7) + (((row & 7) << 4) ^ bcol));
                bf[up * 2 + 0][0] = r4[0]; bf[up * 2 + 0][1] = r4[1];
                bf[up * 2 + 1][0] = r4[2]; bf[up * 2 + 1][1] = r4[3];
            }
            #pragma unroll
            for (int t = 0; t < 4; t++)
                #pragma unroll
                for (int u = 0; u < 4; u++)
                    mma_tf32(acc[t][u], af[t], bf[u]);
        }
        __syncthreads();
        if (s + 2 < NSTG) load_stage(s + 2, buf);
    }

    // ---- epilogue ----
    #pragma unroll
    for (int t = 0; t < 4; t++) {
        #pragma unroll
        for (int half = 0; half < 2; half++) {
            const int gm = bm + wm + t * 16 + g + half * 8;
            if (gm >= M) continue;
            const size_t orow = cmap ? (size_t)cmap[gm] : (size_t)gm;
            const float* ap = addwin ? addwin + (size_t)(gm >> 4) * 512 : nullptr;
            const int colb = bn + wn + 2 * q;
            #pragma unroll
            for (int u = 0; u < 4; u++) {
                const int col = colb + u * 8;
                float o0 = acc[t][u][half * 2 + 0];
                float o1 = acc[t][u][half * 2 + 1];
                if (ap)   { o0 += ap[col];   o1 += ap[col + 1]; }
                if (bias) { o0 += bias[col]; o1 += bias[col + 1]; }
                if (roundOut) { o0 = tf32r(o0); o1 = tf32r(o1); }
                *(float2*)(C + orow * ldc + col) = make_float2(o0, o1);
            }
        }
    }
}

// ---------------- 16x16 local window attention (per window, per head) ------
#define QK_PAD 68

__global__ __launch_bounds__(256)
void k_attn(const float* __restrict__ qkv, float* __restrict__ xh) {
    const int widx = blockIdx.x;
    const int h = blockIdx.y;

    __shared__ float q[16][QK_PAD];
    __shared__ float k[16][QK_PAD];
    __shared__ float v[16][QK_PAD];
    __shared__ float S[16][17];
    __shared__ float rmax[16], rsum[16];

    const int tid = threadIdx.x;
    const int t = tid >> 4;
    const int c4 = (tid & 15) * 4;

    const float* base = qkv + ((size_t)(widx * 16 + t)) * 1536 + h * HD + c4;
    *(float4*)&q[t][c4] = *(const float4*)(base);
    *(float4*)&k[t][c4] = *(const float4*)(base + 512);
    *(float4*)&v[t][c4] = *(const float4*)(base + 1024);
    __syncthreads();

    const int i = tid >> 4;
    const int j = tid & 15;
    float s = 0.f;
    #pragma unroll
    for (int d = 0; d < HD; d++) s = fmaf(q[i][d], k[j][d], s);
    S[i][j] = s * SCALE;
    __syncthreads();

    if (j == 0) {
        float m = S[i][0];
        #pragma unroll
        for (int jj = 1; jj < 16; jj++) m = fmaxf(m, S[i][jj]);
        rmax[i] = m;
    }
    __syncthreads();
    S[i][j] = expf(S[i][j] - rmax[i]);
    __syncthreads();
    if (j == 0) {
        float su = 0.f;
        #pragma unroll
        for (int jj = 0; jj < 16; jj++) su += S[i][jj];
        rsum[i] = 1.0f / su;
    }
    __syncthreads();

    #pragma unroll
    for (int it = 0; it < 4; it++) {
        const int idx = tid + it * 256;
        const int oi = idx >> 6;
        const int d = idx & 63;
        const float rs = rsum[oi];
        float acc = 0.f;
        #pragma unroll
        for (int jj = 0; jj < 16; jj++) acc = fmaf(S[oi][jj] * rs, v[jj][d], acc);
        // round to tf32: xh feeds the projection GEMM as an A operand
        xh[((size_t)(widx * 16 + oi)) * 512 + h * HD + d] = tf32r(acc);
    }
}

// ---------------- launch ---------------------------------------------------
#define TC_SMEM (2 * STG_BYTES)   // 65536 bytes

extern "C" void kernel_launch(void* const* d_in, const int* in_sizes, int n_in,
                              void* d_out, int out_size) {
    const float* x        = (const float*)d_in[0];
    const float* w_qkv_h  = (const float*)d_in[1];
    const float* w_qkv_l  = (const float*)d_in[2];
    const float* w_proj   = (const float*)d_in[3];
    const float* b_proj   = (const float*)d_in[4];
    float* out = (float*)d_out;

    float *qkv, *xg, *xh, *xavg, *vl, *yl, *wqkv, *wvl, *wp1, *wp2;
    int* ridx;
    cudaGetSymbolAddress((void**)&qkv,  g_qkv);
    cudaGetSymbolAddress((void**)&xg,   g_xg);
    cudaGetSymbolAddress((void**)&xh,   g_xh);
    cudaGetSymbolAddress((void**)&xavg, g_xavg);
    cudaGetSymbolAddress((void**)&vl,   g_vl);
    cudaGetSymbolAddress((void**)&yl,   g_yl);
    cudaGetSymbolAddress((void**)&wqkv, g_wqkv);
    cudaGetSymbolAddress((void**)&wvl,  g_wvl);
    cudaGetSymbolAddress((void**)&wp1,  g_wp1);
    cudaGetSymbolAddress((void**)&wp2,  g_wp2);
    cudaGetSymbolAddress((void**)&ridx, g_rowidx);

    cudaFuncSetAttribute(tc_gemm, cudaFuncAttributeMaxDynamicSharedMemorySize, TC_SMEM);

    // 1. token index map
    k_rowidx<<<(NTOK + 255) / 256, 256>>>(ridx);

    // 2. prep: gather+round x, pool, round weights
    k_gather<<<NTOK / 2, 256>>>(x, ridx, xg);
    k_avg<<<NWIN, 128>>>(x, ridx, xavg);
    k_roundcopy<<<(1536 * 128 + 255) / 256, 256>>>(w_qkv_h, wqkv, 1536 * 128);
    k_roundcopy<<<(512 * 128 + 255) / 256, 256>>>(w_qkv_l + (size_t)1024 * 512, wvl, 512 * 128);
    k_packproj<<<(512 * 128 + 255) / 256, 256>>>(w_proj, wp1, wp2);

    // 3. global branch (softmax over 1 token == identity): vl = xavg @ Wv_l^T
    tc_gemm<<<dim3(512 / GBN, (NWIN + GBM - 1) / GBM), 256, TC_SMEM>>>(
        xavg, wvl, vl, 512, nullptr, nullptr, nullptr, NWIN, 1);

    // 4. yl = vl @ Wp2^T
    tc_gemm<<<dim3(512 / GBN, (NWIN + GBM - 1) / GBM), 256, TC_SMEM>>>(
        vl, wp2, yl, 512, nullptr, nullptr, nullptr, NWIN, 0);

    // 5. local branch qkv = xg @ w_qkv_h^T  -> [NTOK, 1536]
    tc_gemm<<<dim3(1536 / GBN, NTOK / GBM), 256, TC_SMEM>>>(
        xg, wqkv, qkv, 1536, nullptr, nullptr, nullptr, NTOK, 0);

    // 6. 16x16 window attention per (window, head)
    k_attn<<<dim3(NWIN, NHEAD), 256>>>(qkv, xh);

    // 7. out = scatter( xh @ Wp1^T + yl[window] + bias )
    tc_gemm<<<dim3(512 / GBN, NTOK / GBM), 256, TC_SMEM>>>(
        xh, wp1, out, 512, ridx, yl, b_proj, NTOK, 0);
}

// round 5
// speedup vs baseline: 3.8728x; 1.0384x over previous
#include <cuda_runtime.h>
#include <math.h>
#include <stdint.h>

// Problem constants
#define B_DIM 16
#define H_DIM 56
#define W_DIM 56
#define C_DIM 512
#define NHEAD 8
#define HD 64
#define WS 4
#define NWIN 3136      // 16 * 14 * 14
#define NTOK 50176     // NWIN * 16
#define SCALE 0.04419417382415922f   // 512^-0.5

// ---------------- scratch (static device globals; no allocation) -----------
__device__ float g_qkv[(size_t)NTOK * 1536];   // qkv of local branch
__device__ float g_xg[(size_t)NTOK * 512];     // gathered + tf32-rounded x
__device__ float g_xh[(size_t)NTOK * 512];     // local attention out (rounded)
__device__ float g_xavg[NWIN * 512];           // pooled window tokens (rounded)
__device__ float g_vl[NWIN * 512];             // v of global branch (rounded)
__device__ float g_yl[NWIN * 512];             // vl @ Wp2^T (per-window add)
__device__ float g_wqkv[1536 * 512];           // rounded w_qkv_h
__device__ float g_wvl[512 * 512];             // rounded w_qkv_l v-part
__device__ float g_wp1[512 * 512];             // rounded w_proj[:, :512]
__device__ float g_wp2[512 * 512];             // rounded w_proj[:, 512:]
__device__ int   g_rowidx[NTOK];               // gt -> token row in x / out

// ---------------- small helpers --------------------------------------------
__device__ __forceinline__ float tf32r(float f) {
    uint32_t r;
    asm("cvt.rna.tf32.f32 %0, %1;" : "=r"(r) : "f"(f));
    return __uint_as_float(r);
}

__device__ __forceinline__ uint32_t smem_u32(const void* p) {
    uint32_t a;
    asm("{ .reg .u64 t; cvta.to.shared.u64 t, %1; cvt.u32.u64 %0, t; }" : "=r"(a) : "l"(p));
    return a;
}

__device__ __forceinline__ void cpasync16(uint32_t dst, const void* src) {
    asm volatile("cp.async.cg.shared.global [%0], [%1], 16;" :: "r"(dst), "l"(src) : "memory");
}

__device__ __forceinline__ void ldsm_x4(uint32_t r[4], uint32_t addr) {
    asm volatile("ldmatrix.sync.aligned.m8n8.x4.shared.b16 {%0,%1,%2,%3}, [%4];"
                 : "=r"(r[0]), "=r"(r[1]), "=r"(r[2]), "=r"(r[3]) : "r"(addr));
}

__device__ __forceinline__ void mma_tf32(float c[4], const uint32_t a[4], const uint32_t b[2]) {
    asm volatile(
        "mma.sync.aligned.m16n8k8.row.col.f32.tf32.tf32.f32 "
        "{%0,%1,%2,%3}, {%4,%5,%6,%7}, {%8,%9}, {%0,%1,%2,%3};"
        : "+f"(c[0]), "+f"(c[1]), "+f"(c[2]), "+f"(c[3])
        : "r"(a[0]), "r"(a[1]), "r"(a[2]), "r"(a[3]), "r"(b[0]), "r"(b[1]));
}

// ---------------- index map: window-token order -> spatial row -------------
__global__ void k_rowidx(int* __restrict__ ridx) {
    int gt = blockIdx.x * 256 + threadIdx.x;
    if (gt >= NTOK) return;
    int widx = gt >> 4, t = gt & 15;
    int b = widx / 196;
    int rem = widx % 196;
    int wh = rem / 14, ww = rem % 14;
    int row = wh * WS + (t >> 2);
    int col = ww * WS + (t & 3);
    ridx[gt] = (b * H_DIM + row) * W_DIM + col;
}

// ---------------- gather x into window order + tf32 round ------------------
// grid-stride over NTOK*128 float4 elements
__global__ void k_gather(const float* __restrict__ x, const int* __restrict__ ridx,
                         float* __restrict__ xg) {
    const int total = NTOK * 128;
    for (int idx = blockIdx.x * 256 + threadIdx.x; idx < total; idx += gridDim.x * 256) {
        int gt = idx >> 7;
        int c = (idx & 127) * 4;
        const float4 v = *(const float4*)(x + (size_t)ridx[gt] * C_DIM + c);
        float4 o = make_float4(tf32r(v.x), tf32r(v.y), tf32r(v.z), tf32r(v.w));
        *(float4*)(xg + (size_t)gt * C_DIM + c) = o;
    }
}

// ---------------- per-window average pooling (rounded output) --------------
__global__ void k_avg(const float* __restrict__ x, const int* __restrict__ ridx,
                      float* __restrict__ xavg) {
    int widx = blockIdx.x;
    int c = threadIdx.x * 4;
    float4 s = make_float4(0.f, 0.f, 0.f, 0.f);
    #pragma unroll
    for (int t = 0; t < 16; t++) {
        const float4 v = *(const float4*)(x + (size_t)ridx[widx * 16 + t] * C_DIM + c);
        s.x += v.x; s.y += v.y; s.z += v.z; s.w += v.w;
    }
    const float inv = 1.0f / 16.0f;
    float4 o = make_float4(tf32r(s.x * inv), tf32r(s.y * inv),
                           tf32r(s.z * inv), tf32r(s.w * inv));
    *(float4*)(xavg + (size_t)widx * C_DIM + c) = o;
}

// ---------------- merged weight rounding / packing -------------------------
// idx space (float4 units):
//   [0, 196608)           : wqkv    <- w_qkv_h (1536x512)
//   [196608, 262144)      : wvl     <- w_qkv_l rows [1024:1536)
//   [262144, 327680)      : wp1/wp2 <- w_proj split (each idx makes 2 outputs)
__global__ void k_wprep(const float* __restrict__ wqkvh, const float* __restrict__ wqkvl,
                        const float* __restrict__ wproj,
                        float* __restrict__ wqkv, float* __restrict__ wvl,
                        float* __restrict__ wp1, float* __restrict__ wp2) {
    const int total = 196608 + 65536 + 65536;
    for (int i = blockIdx.x * 256 + threadIdx.x; i < total; i += gridDim.x * 256) {
        if (i < 196608) {
            float4 v = *(const float4*)(wqkvh + (size_t)i * 4);
            *(float4*)(wqkv + (size_t)i * 4) =
                make_float4(tf32r(v.x), tf32r(v.y), tf32r(v.z), tf32r(v.w));
        } else if (i < 262144) {
            int j = i - 196608;
            float4 v = *(const float4*)(wqkvl + (size_t)(1024 * 512) + (size_t)j * 4);
            *(float4*)(wvl + (size_t)j * 4) =
                make_float4(tf32r(v.x), tf32r(v.y), tf32r(v.z), tf32r(v.w));
        } else {
            int j = i - 262144;
            int n = j >> 7, k4 = (j & 127) * 4;
            float4 a = *(const float4*)(wproj + (size_t)n * 1024 + k4);
            float4 b = *(const float4*)(wproj + (size_t)n * 1024 + 512 + k4);
            *(float4*)(wp1 + (size_t)n * 512 + k4) =
                make_float4(tf32r(a.x), tf32r(a.y), tf32r(a.z), tf32r(a.w));
            *(float4*)(wp2 + (size_t)n * 512 + k4) =
                make_float4(tf32r(b.x), tf32r(b.y), tf32r(b.z), tf32r(b.w));
        }
    }
}

// ---------------- tf32 tensor GEMM: C = A * B^T ----------------------------
// A: [M, 512] tf32-rounded fp32 (rows clamped at M edge)
// B: [N, 512] tf32-rounded fp32, N multiple of 128
// C: [M, ldc] optional row scatter (cmap), += addwin[m>>4][col], += bias[col],
//    optional tf32 rounding of the output.
// BM=BN=128, BK=32, 3-stage cp.async pipeline, ldmatrix fragment loads.
// Warp tile 64x32: warps 2(M) x 4(N); per warp 4x4 m16n8 tiles.
#define GBM 128
#define GBN 128
#define GBK 32
#define GK  512
#define NSTG (GK / GBK)        // 16 k-slabs
#define STG_BYTES 32768        // (128 A rows + 128 B rows) * 128 B
#define NPIPE 3

__global__ __launch_bounds__(256, 2)
void tc_gemm(const float* __restrict__ A, const float* __restrict__ B,
             float* __restrict__ C, int ldc,
             const int* __restrict__ cmap, const float* __restrict__ addwin,
             const float* __restrict__ bias, int M, int roundOut) {
    extern __shared__ char smem[];
    const uint32_t sbase = smem_u32(smem);

    const int tid  = threadIdx.x;
    const int warp = tid >> 5;
    const int lane = tid & 31;
    const int g = lane >> 2;
    const int q = lane & 3;
    const int wm = (warp >> 2) * 64;
    const int wn = (warp & 3) * 32;
    const int bm = blockIdx.y * GBM;
    const int bn = blockIdx.x * GBN;

    // ldmatrix address components (swizzle: col ^= (row&7)<<4)
    const int mid = lane >> 3;          // matrix id 0..3
    const int r7  = lane & 7;
    const int aRow0 = wm + (mid & 1) * 8 + r7;       // + t*16
    const int aHalf = (mid >> 1) * 16;
    const int bRow0 = wn + (mid >> 1) * 8 + r7;      // + upair*16
    const int bHalf = (mid & 1) * 16;

    float acc[4][4][4];
    #pragma unroll
    for (int t = 0; t < 4; t++)
        #pragma unroll
        for (int u = 0; u < 4; u++)
            #pragma unroll
            for (int r = 0; r < 4; r++) acc[t][u][r] = 0.f;

    // stage loader: 4 A-chunks + 4 B-chunks of 16B per thread
    auto load_stage = [&](int s, int buf) {
        const int k0 = s * GBK;
        const uint32_t so = sbase + buf * STG_BYTES;
        #pragma unroll
        for (int i = 0; i < 4; i++) {
            int idx = tid + i * 256;          // 0..1023
            int r = idx >> 3, hc = idx & 7;
            int grow = bm + r; if (grow >= M) grow = M - 1;
            uint32_t off = (uint32_t)(r * 128 + hc * 16);
            cpasync16(so + (off ^ ((off >> 3) & 0x70)),
                      A + (size_t)grow * GK + k0 + hc * 4);
        }
        #pragma unroll
        for (int i = 0; i < 4; i++) {
            int idx = tid + i * 256;
            int r = idx >> 3, hc = idx & 7;
            uint32_t off = (uint32_t)(r * 128 + hc * 16);
            cpasync16(so + 16384 + (off ^ ((off >> 3) & 0x70)),
                      B + (size_t)(bn + r) * GK + k0 + hc * 4);
        }
        asm volatile("cp.async.commit_group;" ::: "memory");
    };

    load_stage(0, 0);
    load_stage(1, 1);
    load_stage(2, 2);

    for (int s = 0; s < NSTG; s++) {
        const int buf = s % NPIPE;
        if (s <= NSTG - 3)      asm volatile("cp.async.wait_group 2;" ::: "memory");
        else if (s == NSTG - 2) asm volatile("cp.async.wait_group 1;" ::: "memory");
        else                    asm volatile("cp.async.wait_group 0;" ::: "memory");
        __syncthreads();

        const uint32_t sA = sbase + buf * STG_BYTES;
        const uint32_t sB = sA + 16384;

        #pragma unroll
        for (int kk = 0; kk < 4; kk++) {
            const uint32_t acol = (uint32_t)(kk * 32 + aHalf);
            const uint32_t bcol = (uint32_t)(kk * 32 + bHalf);
            uint32_t af[4][4];
            #pragma unroll
            for (int t = 0; t < 4; t++) {
                const uint32_t row = (uint32_t)(aRow0 + t * 16);
                ldsm_x4(af[t], sA + (row << 7) + (((row & 7) << 4) ^ acol));
            }
            uint32_t bf[4][2];
            #pragma unroll
            for (int up = 0; up < 2; up++) {
                uint32_t r4[4];
                const uint32_t row = (uint32_t)(bRow0 + up * 16);
                ldsm_x4(r4, sB + (row << 7) + (((row & 7) << 4) ^ bcol));
                bf[up * 2 + 0][0] = r4[0]; bf[up * 2 + 0][1] = r4[1];
                bf[up * 2 + 1][0] = r4[2]; bf[up * 2 + 1][1] = r4[3];
            }
            #pragma unroll
            for (int t = 0; t < 4; t++)
                #pragma unroll
                for (int u = 0; u < 4; u++)
                    mma_tf32(acc[t][u], af[t], bf[u]);
        }
        __syncthreads();
        if (s + NPIPE < NSTG) load_stage(s + NPIPE, buf);
    }

    // ---- epilogue ----
    #pragma unroll
    for (int t = 0; t < 4; t++) {
        #pragma unroll
        for (int half = 0; half < 2; half++) {
            const int gm = bm + wm + t * 16 + g + half * 8;
            if (gm >= M) continue;
            const size_t orow = cmap ? (size_t)cmap[gm] : (size_t)gm;
            const float* ap = addwin ? addwin + (size_t)(gm >> 4) * 512 : nullptr;
            const int colb = bn + wn + 2 * q;
            #pragma unroll
            for (int u = 0; u < 4; u++) {
                const int col = colb + u * 8;
                float o0 = acc[t][u][half * 2 + 0];
                float o1 = acc[t][u][half * 2 + 1];
                if (ap)   { o0 += ap[col];   o1 += ap[col + 1]; }
                if (bias) { o0 += bias[col]; o1 += bias[col + 1]; }
                if (roundOut) { o0 = tf32r(o0); o1 = tf32r(o1); }
                *(float2*)(C + orow * ldc + col) = make_float2(o0, o1);
            }
        }
    }
}

// ---------------- 16x16 local window attention (per window, per head) ------
#define QK_PAD 68

__global__ __launch_bounds__(256)
void k_attn(const float* __restrict__ qkv, float* __restrict__ xh) {
    const int widx = blockIdx.x;
    const int h = blockIdx.y;

    __shared__ float q[16][QK_PAD];
    __shared__ float k[16][QK_PAD];
    __shared__ float v[16][QK_PAD];
    __shared__ float S[16][17];

    const int tid = threadIdx.x;
    const int t = tid >> 4;
    const int c4 = (tid & 15) * 4;

    const float* base = qkv + ((size_t)(widx * 16 + t)) * 1536 + h * HD + c4;
    *(float4*)&q[t][c4] = *(const float4*)(base);
    *(float4*)&k[t][c4] = *(const float4*)(base + 512);
    *(float4*)&v[t][c4] = *(const float4*)(base + 1024);
    __syncthreads();

    const int i = tid >> 4;
    const int j = tid & 15;
    float s = 0.f;
    #pragma unroll
    for (int d = 0; d < HD; d++) s = fmaf(q[i][d], k[j][d], s);
    s *= SCALE;

    // softmax over the 16-lane group that shares row i (lanes j=0..15)
    float m = s;
    #pragma unroll
    for (int o = 8; o >= 1; o >>= 1)
        m = fmaxf(m, __shfl_xor_sync(0xffffffffu, m, o, 16));
    float e = expf(s - m);
    float su = e;
    #pragma unroll
    for (int o = 8; o >= 1; o >>= 1)
        su += __shfl_xor_sync(0xffffffffu, su, o, 16);
    S[i][j] = e * __frcp_rn(su);        // normalized probability
    __syncthreads();

    // out[i][d] = sum_j P[i][j] * v[j][d]; 1024 outputs over 256 threads
    #pragma unroll
    for (int it = 0; it < 4; it++) {
        const int idx = tid + it * 256;
        const int oi = idx >> 6;
        const int d = idx & 63;
        float acc = 0.f;
        #pragma unroll
        for (int jj = 0; jj < 16; jj++) acc = fmaf(S[oi][jj], v[jj][d], acc);
        // round to tf32: xh feeds the projection GEMM as an A operand
        xh[((size_t)(widx * 16 + oi)) * 512 + h * HD + d] = tf32r(acc);
    }
}

// ---------------- launch ---------------------------------------------------
#define TC_SMEM (NPIPE * STG_BYTES)   // 98304 bytes

extern "C" void kernel_launch(void* const* d_in, const int* in_sizes, int n_in,
                              void* d_out, int out_size) {
    const float* x        = (const float*)d_in[0];
    const float* w_qkv_h  = (const float*)d_in[1];
    const float* w_qkv_l  = (const float*)d_in[2];
    const float* w_proj   = (const float*)d_in[3];
    const float* b_proj   = (const float*)d_in[4];
    float* out = (float*)d_out;

    float *qkv, *xg, *xh, *xavg, *vl, *yl, *wqkv, *wvl, *wp1, *wp2;
    int* ridx;
    cudaGetSymbolAddress((void**)&qkv,  g_qkv);
    cudaGetSymbolAddress((void**)&xg,   g_xg);
    cudaGetSymbolAddress((void**)&xh,   g_xh);
    cudaGetSymbolAddress((void**)&xavg, g_xavg);
    cudaGetSymbolAddress((void**)&vl,   g_vl);
    cudaGetSymbolAddress((void**)&yl,   g_yl);
    cudaGetSymbolAddress((void**)&wqkv, g_wqkv);
    cudaGetSymbolAddress((void**)&wvl,  g_wvl);
    cudaGetSymbolAddress((void**)&wp1,  g_wp1);
    cudaGetSymbolAddress((void**)&wp2,  g_wp2);
    cudaGetSymbolAddress((void**)&ridx, g_rowidx);

    cudaFuncSetAttribute(tc_gemm, cudaFuncAttributeMaxDynamicSharedMemorySize, TC_SMEM);

    // 1. token index map
    k_rowidx<<<(NTOK + 255) / 256, 256>>>(ridx);

    // 2. prep: gather+round x, pool, round weights
    k_gather<<<2048, 256>>>(x, ridx, xg);
    k_avg<<<NWIN, 128>>>(x, ridx, xavg);
    k_wprep<<<1280, 256>>>(w_qkv_h, w_qkv_l, w_proj, wqkv, wvl, wp1, wp2);

    // 3. global branch (softmax over 1 token == identity): vl = xavg @ Wv_l^T
    tc_gemm<<<dim3(512 / GBN, (NWIN + GBM - 1) / GBM), 256, TC_SMEM>>>(
        xavg, wvl, vl, 512, nullptr, nullptr, nullptr, NWIN, 1);

    // 4. yl = vl @ Wp2^T
    tc_gemm<<<dim3(512 / GBN, (NWIN + GBM - 1) / GBM), 256, TC_SMEM>>>(
        vl, wp2, yl, 512, nullptr, nullptr, nullptr, NWIN, 0);

    // 5. local branch qkv = xg @ w_qkv_h^T  -> [NTOK, 1536]
    tc_gemm<<<dim3(1536 / GBN, NTOK / GBM), 256, TC_SMEM>>>(
        xg, wqkv, qkv, 1536, nullptr, nullptr, nullptr, NTOK, 0);

    // 6. 16x16 window attention per (window, head)
    k_attn<<<dim3(NWIN, NHEAD), 256>>>(qkv, xh);

    // 7. out = scatter( xh @ Wp1^T + yl[window] + bias )
    tc_gemm<<<dim3(512 / GBN, NTOK / GBM), 256, TC_SMEM>>>(
        xh, wp1, out, 512, ridx, yl, b_proj, NTOK, 0);
}

// round 6
// speedup vs baseline: 5.7879x; 1.4945x over previous
#include <cuda_runtime.h>
#include <cuda_fp16.h>
#include <math.h>
#include <stdint.h>

// Problem constants
#define B_DIM 16
#define H_DIM 56
#define W_DIM 56
#define C_DIM 512
#define NHEAD 8
#define HD 64
#define WS 4
#define NWIN 3136      // 16 * 14 * 14
#define NTOK 50176     // NWIN * 16
#define SCALE 0.04419417382415922f   // 512^-0.5

// ---------------- scratch (static device globals; no allocation) -----------
__device__ __half g_qkv[(size_t)NTOK * 1536]; // qkv of local branch (fp16)
__device__ __half g_xg[(size_t)NTOK * 512];   // gathered x (fp16)
__device__ __half g_xh[(size_t)NTOK * 512];   // local attention out (fp16)
__device__ __half g_xavg[NWIN * 512];         // pooled window tokens (fp16)
__device__ __half g_vl[NWIN * 512];           // v of global branch (fp16)
__device__ float  g_yl[NWIN * 512];           // vl @ Wp2^T (fp32 window add)
__device__ __half g_wqkv[1536 * 512];         // fp16 w_qkv_h
__device__ __half g_wvl[512 * 512];           // fp16 w_qkv_l v-part
__device__ __half g_wp1[512 * 512];           // fp16 w_proj[:, :512]
__device__ __half g_wp2[512 * 512];           // fp16 w_proj[:, 512:]
__device__ int    g_rowidx[NTOK];             // gt -> token row in x / out

// ---------------- small helpers --------------------------------------------
__device__ __forceinline__ uint32_t smem_u32(const void* p) {
    uint32_t a;
    asm("{ .reg .u64 t; cvta.to.shared.u64 t, %1; cvt.u32.u64 %0, t; }" : "=r"(a) : "l"(p));
    return a;
}

__device__ __forceinline__ void cpasync16(uint32_t dst, const void* src) {
    asm volatile("cp.async.cg.shared.global [%0], [%1], 16;" :: "r"(dst), "l"(src) : "memory");
}

__device__ __forceinline__ void ldsm_x4(uint32_t r[4], uint32_t addr) {
    asm volatile("ldmatrix.sync.aligned.m8n8.x4.shared.b16 {%0,%1,%2,%3}, [%4];"
                 : "=r"(r[0]), "=r"(r[1]), "=r"(r[2]), "=r"(r[3]) : "r"(addr));
}

__device__ __forceinline__ void mma_fp16(float c[4], const uint32_t a[4], const uint32_t b[2]) {
    asm volatile(
        "mma.sync.aligned.m16n8k16.row.col.f32.f16.f16.f32 "
        "{%0,%1,%2,%3}, {%4,%5,%6,%7}, {%8,%9}, {%0,%1,%2,%3};"
        : "+f"(c[0]), "+f"(c[1]), "+f"(c[2]), "+f"(c[3])
        : "r"(a[0]), "r"(a[1]), "r"(a[2]), "r"(a[3]), "r"(b[0]), "r"(b[1]));
}

__device__ __forceinline__ uint32_t pack_h2(float a, float b) {
    __half2 h = __floats2half2_rn(a, b);
    return *(uint32_t*)&h;
}

// ---------------- index map: window-token order -> spatial row -------------
__global__ void k_rowidx(int* __restrict__ ridx) {
    int gt = blockIdx.x * 256 + threadIdx.x;
    if (gt >= NTOK) return;
    int widx = gt >> 4, t = gt & 15;
    int b = widx / 196;
    int rem = widx % 196;
    int wh = rem / 14, ww = rem % 14;
    int row = wh * WS + (t >> 2);
    int col = ww * WS + (t & 3);
    ridx[gt] = (b * H_DIM + row) * W_DIM + col;
}

// ---------------- gather x into window order -> fp16 -----------------------
__global__ void k_gather(const float* __restrict__ x, const int* __restrict__ ridx,
                         __half* __restrict__ xg) {
    const int total = NTOK * 128;
    for (int idx = blockIdx.x * 256 + threadIdx.x; idx < total; idx += gridDim.x * 256) {
        int gt = idx >> 7;
        int c = (idx & 127) * 4;
        const float4 v = *(const float4*)(x + (size_t)ridx[gt] * C_DIM + c);
        uint2 o = make_uint2(pack_h2(v.x, v.y), pack_h2(v.z, v.w));
        *(uint2*)(xg + (size_t)gt * C_DIM + c) = o;
    }
}

// ---------------- per-window average pooling -> fp16 -----------------------
__global__ void k_avg(const float* __restrict__ x, const int* __restrict__ ridx,
                      __half* __restrict__ xavg) {
    int widx = blockIdx.x;
    int c = threadIdx.x * 4;
    float4 s = make_float4(0.f, 0.f, 0.f, 0.f);
    #pragma unroll
    for (int t = 0; t < 16; t++) {
        const float4 v = *(const float4*)(x + (size_t)ridx[widx * 16 + t] * C_DIM + c);
        s.x += v.x; s.y += v.y; s.z += v.z; s.w += v.w;
    }
    const float inv = 1.0f / 16.0f;
    uint2 o = make_uint2(pack_h2(s.x * inv, s.y * inv), pack_h2(s.z * inv, s.w * inv));
    *(uint2*)(xavg + (size_t)widx * C_DIM + c) = o;
}

// ---------------- merged weight conversion to fp16 -------------------------
__global__ void k_wprep(const float* __restrict__ wqkvh, const float* __restrict__ wqkvl,
                        const float* __restrict__ wproj,
                        __half* __restrict__ wqkv, __half* __restrict__ wvl,
                        __half* __restrict__ wp1, __half* __restrict__ wp2) {
    const int total = 196608 + 65536 + 65536;
    for (int i = blockIdx.x * 256 + threadIdx.x; i < total; i += gridDim.x * 256) {
        if (i < 196608) {
            float4 v = *(const float4*)(wqkvh + (size_t)i * 4);
            *(uint2*)(wqkv + (size_t)i * 4) =
                make_uint2(pack_h2(v.x, v.y), pack_h2(v.z, v.w));
        } else if (i < 262144) {
            int j = i - 196608;
            float4 v = *(const float4*)(wqkvl + (size_t)(1024 * 512) + (size_t)j * 4);
            *(uint2*)(wvl + (size_t)j * 4) =
                make_uint2(pack_h2(v.x, v.y), pack_h2(v.z, v.w));
        } else {
            int j = i - 262144;
            int n = j >> 7, k4 = (j & 127) * 4;
            float4 a = *(const float4*)(wproj + (size_t)n * 1024 + k4);
            float4 b = *(const float4*)(wproj + (size_t)n * 1024 + 512 + k4);
            *(uint2*)(wp1 + (size_t)n * 512 + k4) =
                make_uint2(pack_h2(a.x, a.y), pack_h2(a.z, a.w));
            *(uint2*)(wp2 + (size_t)n * 512 + k4) =
                make_uint2(pack_h2(b.x, b.y), pack_h2(b.z, b.w));
        }
    }
}

// ---------------- fp16 tensor GEMM: C = A * B^T ----------------------------
// A: [M, 512] fp16 (rows clamped at M edge); B: [N, 512] fp16, N mult of 128.
// C: fp16 (outHalf=1) or fp32; optional row scatter cmap, += addwin (fp32),
//    += bias (fp32).
// BM=BN=128, BK=64 halves (128B rows, SW128), 3-stage cp.async pipeline.
// Warp tile 64x32: 4x4 m16n8k16 tiles per warp per k16-step.
#define GBM 128
#define GBN 128
#define GBK 64
#define GK  512
#define NSTG (GK / GBK)        // 8 k-slabs
#define STG_BYTES 32768        // (128 A rows + 128 B rows) * 128 B
#define NPIPE 3

__global__ __launch_bounds__(256, 2)
void tc_gemm(const __half* __restrict__ A, const __half* __restrict__ B,
             void* __restrict__ Cv, int ldc,
             const int* __restrict__ cmap, const float* __restrict__ addwin,
             const float* __restrict__ bias, int M, int outHalf) {
    extern __shared__ char smem[];
    const uint32_t sbase = smem_u32(smem);

    const int tid  = threadIdx.x;
    const int warp = tid >> 5;
    const int lane = tid & 31;
    const int g = lane >> 2;
    const int q = lane & 3;
    const int wm = (warp >> 2) * 64;
    const int wn = (warp & 3) * 32;
    const int bm = blockIdx.y * GBM;
    const int bn = blockIdx.x * GBN;

    // ldmatrix lane -> (row, 16B-half) mapping
    const int mid = lane >> 3;          // matrix id 0..3
    const int r7  = lane & 7;
    // A x4: m0=(rows0-7,kb0) m1=(rows8-15,kb0) m2=(rows0-7,kb1) m3=(rows8-15,kb1)
    const int aRow0 = wm + (mid & 1) * 8 + r7;       // + t*16
    const int aHalf = (mid >> 1) * 16;               // kb byte offset
    // B x4: m0=(n0-7,kb0) m1=(n0-7,kb1) m2=(n8-15,kb0) m3=(n8-15,kb1)
    const int bRow0 = wn + (mid >> 1) * 8 + r7;      // + upair*16
    const int bHalf = (mid & 1) * 16;

    float acc[4][4][4];
    #pragma unroll
    for (int t = 0; t < 4; t++)
        #pragma unroll
        for (int u = 0; u < 4; u++)
            #pragma unroll
            for (int r = 0; r < 4; r++) acc[t][u][r] = 0.f;

    // stage loader: 4 A-chunks + 4 B-chunks of 16B (8 halves) per thread
    auto load_stage = [&](int s, int buf) {
        const int k0 = s * GBK;
        const uint32_t so = sbase + buf * STG_BYTES;
        #pragma unroll
        for (int i = 0; i < 4; i++) {
            int idx = tid + i * 256;          // 0..1023
            int r = idx >> 3, hc = idx & 7;
            int grow = bm + r; if (grow >= M) grow = M - 1;
            uint32_t off = (uint32_t)(r * 128 + hc * 16);
            cpasync16(so + (off ^ ((off >> 3) & 0x70)),
                      A + (size_t)grow * GK + k0 + hc * 8);
        }
        #pragma unroll
        for (int i = 0; i < 4; i++) {
            int idx = tid + i * 256;
            int r = idx >> 3, hc = idx & 7;
            uint32_t off = (uint32_t)(r * 128 + hc * 16);
            cpasync16(so + 16384 + (off ^ ((off >> 3) & 0x70)),
                      B + (size_t)(bn + r) * GK + k0 + hc * 8);
        }
        asm volatile("cp.async.commit_group;" ::: "memory");
    };

    load_stage(0, 0);
    load_stage(1, 1);
    load_stage(2, 2);

    for (int s = 0; s < NSTG; s++) {
        const int buf = s % NPIPE;
        if (s <= NSTG - 3)      asm volatile("cp.async.wait_group 2;" ::: "memory");
        else if (s == NSTG - 2) asm volatile("cp.async.wait_group 1;" ::: "memory");
        else                    asm volatile("cp.async.wait_group 0;" ::: "memory");
        __syncthreads();

        const uint32_t sA = sbase + buf * STG_BYTES;
        const uint32_t sB = sA + 16384;

        #pragma unroll
        for (int kk = 0; kk < 4; kk++) {           // 4 k16-steps per 64-k slab
            const uint32_t acol = (uint32_t)(kk * 32 + aHalf);
            const uint32_t bcol = (uint32_t)(kk * 32 + bHalf);
            uint32_t af[4][4];
            #pragma unroll
            for (int t = 0; t < 4; t++) {
                const uint32_t row = (uint32_t)(aRow0 + t * 16);
                ldsm_x4(af[t], sA + (row << 7) + (((row & 7) << 4) ^ acol));
            }
            uint32_t bf[4][2];
            #pragma unroll
            for (int up = 0; up < 2; up++) {
                uint32_t r4[4];
                const uint32_t row = (uint32_t)(bRow0 + up * 16);
                ldsm_x4(r4, sB + (row << 7) + (((row & 7) << 4) ^ bcol));
                bf[up * 2 + 0][0] = r4[0]; bf[up * 2 + 0][1] = r4[1];
                bf[up * 2 + 1][0] = r4[2]; bf[up * 2 + 1][1] = r4[3];
            }
            #pragma unroll
            for (int t = 0; t < 4; t++)
                #pragma unroll
                for (int u = 0; u < 4; u++)
                    mma_fp16(acc[t][u], af[t], bf[u]);
        }
        __syncthreads();
        if (s + NPIPE < NSTG) load_stage(s + NPIPE, buf);
    }

    // ---- epilogue ----
    #pragma unroll
    for (int t = 0; t < 4; t++) {
        #pragma unroll
        for (int half = 0; half < 2; half++) {
            const int gm = bm + wm + t * 16 + g + half * 8;
            if (gm >= M) continue;
            const size_t orow = cmap ? (size_t)cmap[gm] : (size_t)gm;
            const float* ap = addwin ? addwin + (size_t)(gm >> 4) * 512 : nullptr;
            const int colb = bn + wn + 2 * q;
            #pragma unroll
            for (int u = 0; u < 4; u++) {
                const int col = colb + u * 8;
                float o0 = acc[t][u][half * 2 + 0];
                float o1 = acc[t][u][half * 2 + 1];
                if (ap)   { o0 += ap[col];   o1 += ap[col + 1]; }
                if (bias) { o0 += bias[col]; o1 += bias[col + 1]; }
                if (outHalf) {
                    *(uint32_t*)((__half*)Cv + orow * ldc + col) = pack_h2(o0, o1);
                } else {
                    *(float2*)((float*)Cv + orow * ldc + col) = make_float2(o0, o1);
                }
            }
        }
    }
}

// ---------------- 16x16 local window attention (per window, per head) ------
#define QK_PAD 68

__global__ __launch_bounds__(256)
void k_attn(const __half* __restrict__ qkv, __half* __restrict__ xh) {
    const int widx = blockIdx.x;
    const int h = blockIdx.y;

    __shared__ float q[16][QK_PAD];
    __shared__ float k[16][QK_PAD];
    __shared__ float v[16][QK_PAD];
    __shared__ float S[16][17];

    const int tid = threadIdx.x;
    const int t = tid >> 4;
    const int c4 = (tid & 15) * 4;

    const __half2* base = (const __half2*)(qkv + (size_t)(widx * 16 + t) * 1536 + h * HD + c4);
    float2 a0 = __half22float2(base[0]);
    float2 a1 = __half22float2(base[1]);
    q[t][c4 + 0] = a0.x; q[t][c4 + 1] = a0.y; q[t][c4 + 2] = a1.x; q[t][c4 + 3] = a1.y;
    const __half2* kb = base + 256;   // +512 halves
    a0 = __half22float2(kb[0]); a1 = __half22float2(kb[1]);
    k[t][c4 + 0] = a0.x; k[t][c4 + 1] = a0.y; k[t][c4 + 2] = a1.x; k[t][c4 + 3] = a1.y;
    const __half2* vb = base + 512;   // +1024 halves
    a0 = __half22float2(vb[0]); a1 = __half22float2(vb[1]);
    v[t][c4 + 0] = a0.x; v[t][c4 + 1] = a0.y; v[t][c4 + 2] = a1.x; v[t][c4 + 3] = a1.y;
    __syncthreads();

    const int i = tid >> 4;
    const int j = tid & 15;
    float s = 0.f;
    #pragma unroll
    for (int d = 0; d < HD; d++) s = fmaf(q[i][d], k[j][d], s);
    s *= SCALE;

    // softmax across the 16-lane group sharing row i
    float m = s;
    #pragma unroll
    for (int o = 8; o >= 1; o >>= 1)
        m = fmaxf(m, __shfl_xor_sync(0xffffffffu, m, o, 16));
    float e = expf(s - m);
    float su = e;
    #pragma unroll
    for (int o = 8; o >= 1; o >>= 1)
        su += __shfl_xor_sync(0xffffffffu, su, o, 16);
    S[i][j] = e * __frcp_rn(su);
    __syncthreads();

    // out[i][d] = sum_j P[i][j] * v[j][d]; 512 half2 outputs over 256 threads
    #pragma unroll
    for (int it = 0; it < 2; it++) {
        const int idx = tid + it * 256;
        const int oi = idx >> 5;
        const int d2 = (idx & 31) * 2;
        float a = 0.f, b = 0.f;
        #pragma unroll
        for (int jj = 0; jj < 16; jj++) {
            const float p = S[oi][jj];
            a = fmaf(p, v[jj][d2], a);
            b = fmaf(p, v[jj][d2 + 1], b);
        }
        *(uint32_t*)(xh + (size_t)(widx * 16 + oi) * 512 + h * HD + d2) = pack_h2(a, b);
    }
}

// ---------------- launch ---------------------------------------------------
#define TC_SMEM (NPIPE * STG_BYTES)   // 98304 bytes

extern "C" void kernel_launch(void* const* d_in, const int* in_sizes, int n_in,
                              void* d_out, int out_size) {
    const float* x        = (const float*)d_in[0];
    const float* w_qkv_h  = (const float*)d_in[1];
    const float* w_qkv_l  = (const float*)d_in[2];
    const float* w_proj   = (const float*)d_in[3];
    const float* b_proj   = (const float*)d_in[4];
    float* out = (float*)d_out;

    __half *qkv, *xg, *xh, *xavg, *vl, *wqkv, *wvl, *wp1, *wp2;
    float *yl;
    int* ridx;
    cudaGetSymbolAddress((void**)&qkv,  g_qkv);
    cudaGetSymbolAddress((void**)&xg,   g_xg);
    cudaGetSymbolAddress((void**)&xh,   g_xh);
    cudaGetSymbolAddress((void**)&xavg, g_xavg);
    cudaGetSymbolAddress((void**)&vl,   g_vl);
    cudaGetSymbolAddress((void**)&yl,   g_yl);
    cudaGetSymbolAddress((void**)&wqkv, g_wqkv);
    cudaGetSymbolAddress((void**)&wvl,  g_wvl);
    cudaGetSymbolAddress((void**)&wp1,  g_wp1);
    cudaGetSymbolAddress((void**)&wp2,  g_wp2);
    cudaGetSymbolAddress((void**)&ridx, g_rowidx);

    cudaFuncSetAttribute(tc_gemm, cudaFuncAttributeMaxDynamicSharedMemorySize, TC_SMEM);

    // 1. token index map
    k_rowidx<<<(NTOK + 255) / 256, 256>>>(ridx);

    // 2. prep: gather x -> fp16, pool -> fp16, weights -> fp16
    k_gather<<<2048, 256>>>(x, ridx, xg);
    k_avg<<<NWIN, 128>>>(x, ridx, xavg);
    k_wprep<<<1280, 256>>>(w_qkv_h, w_qkv_l, w_proj, wqkv, wvl, wp1, wp2);

    // 3. global branch (softmax over 1 token == identity): vl = xavg @ Wv_l^T
    tc_gemm<<<dim3(512 / GBN, (NWIN + GBM - 1) / GBM), 256, TC_SMEM>>>(
        xavg, wvl, vl, 512, nullptr, nullptr, nullptr, NWIN, 1);

    // 4. yl = vl @ Wp2^T  (fp32 out)
    tc_gemm<<<dim3(512 / GBN, (NWIN + GBM - 1) / GBM), 256, TC_SMEM>>>(
        vl, wp2, yl, 512, nullptr, nullptr, nullptr, NWIN, 0);

    // 5. local branch qkv = xg @ w_qkv_h^T -> [NTOK, 1536] fp16
    tc_gemm<<<dim3(1536 / GBN, NTOK / GBM), 256, TC_SMEM>>>(
        xg, wqkv, qkv, 1536, nullptr, nullptr, nullptr, NTOK, 1);

    // 6. 16x16 window attention per (window, head)
    k_attn<<<dim3(NWIN, NHEAD), 256>>>(qkv, xh);

    // 7. out = scatter( xh @ Wp1^T + yl[window] + bias )  (fp32 out)
    tc_gemm<<<dim3(512 / GBN, NTOK / GBM), 256, TC_SMEM>>>(
        xh, wp1, out, 512, ridx, yl, b_proj, NTOK, 0);
}